// round 1
// baseline (speedup 1.0000x reference)
#include <cuda_runtime.h>
#include <math.h>

#define BQ   4
#define CCH  3
#define HH   512
#define WW   512
#define NPL  32
#define TW   64            // tile width  (output pixels)
#define TH   8             // tile height (output pixels)
#define HALO 15
#define SW   (TW + 2*HALO) // 94 valid halo columns
#define SWP  96            // padded shared row stride (floats)
#define SH   (TH + 2*HALO) // 38 halo rows

// Scratch for the per-launch weight table (no allocations allowed).
__device__ float g_gtab[NPL][32];   // zero-padded, centered 31-tap 1D gaussians
__device__ float g_mids[NPL];       // 31 bucket midpoints (f32, reference-exact)

// ---------------------------------------------------------------------------
// Rebuild weights every launch (graph-capturable, deterministic, ~µs).
// Matches the numpy reference: planes = linspace(0,50,32) in f32;
// k = int(2*coc+1), odd-ify, cap 31; sigma = coc/2.355; normalize.
// ---------------------------------------------------------------------------
__global__ void init_weights_kernel() {
    int i = threadIdx.x;
    if (i >= NPL) return;
    const double step = 50.0 / 31.0;
    float cocf = (float)((double)i * step);          // == f32 linspace value
    if (i < NPL - 1) {
        float nxt = (float)((double)(i + 1) * step);
        g_mids[i] = (cocf + nxt) * 0.5f;             // f32 midpoint, as reference
    }
    float row[32];
#pragma unroll
    for (int j = 0; j < 32; j++) row[j] = 0.0f;

    double coc = (double)cocf;
    if (coc < 0.5) {
        row[15] = 1.0f;                              // identity plane
    } else {
        int k = (int)(2.0 * coc + 1.0);
        if ((k & 1) == 0) k += 1;
        if (k > 31) k = 31;
        double sigma  = coc / 2.355;
        double inv2s2 = 1.0 / (2.0 * sigma * sigma);
        int half = k / 2;
        double s = 0.0;
        for (int j = 0; j < k; j++) { double c = j - half; s += exp(-c * c * inv2s2); }
        int off = 15 - half;                         // center k taps in 31-window
        for (int j = 0; j < k; j++) {
            double c = j - half;
            row[off + j] = (float)(exp(-c * c * inv2s2) / s);
        }
    }
#pragma unroll
    for (int j = 0; j < 32; j++) g_gtab[i][j] = row[j];
}

// ---------------------------------------------------------------------------
// Main kernel: per-pixel 31x31 gather with per-pixel 1D weights.
// Block = (32,8). Each thread computes 2 adjacent x-pixels (A,B) x 3 channels.
// Weights (symmetric -> 16 regs per plane) live in registers for the unrolled
// dx loop; runtime-dy weights come from a bank-padded shared table.
// ---------------------------------------------------------------------------
__global__ __launch_bounds__(256, 2)
void defocus_kernel(const float* __restrict__ sharp,
                    const float* __restrict__ coc,
                    float* __restrict__ out) {
    __shared__ float tile[CCH][SH][SWP];   // 43776 B
    __shared__ float gsh[NPL][33];         // 4224 B (pad 33 kills bank conflicts)
    __shared__ float msh[32];              // 128 B   -> total 48128 B (<48KB)

    const int tid = threadIdx.y * 32 + threadIdx.x;
    const int x0 = blockIdx.x * TW;
    const int y0 = blockIdx.y * TH;
    const int b  = blockIdx.z;

    // Stage weight table + midpoints into shared.
    for (int idx = tid; idx < NPL * 32; idx += 256)
        gsh[idx >> 5][idx & 31] = g_gtab[idx >> 5][idx & 31];
    if (tid < 31) msh[tid] = g_mids[tid];

    // Load tile + halo (zero-fill outside image), coalesced along columns.
    const float* sb = sharp + (size_t)b * CCH * HH * WW;
#pragma unroll
    for (int c = 0; c < CCH; c++) {
        const float* sc = sb + (size_t)c * HH * WW;
        for (int idx = tid; idx < SH * SWP; idx += 256) {
            int r  = idx / SWP;
            int cc = idx - r * SWP;
            int gx = x0 - HALO + cc;
            int gy = y0 - HALO + r;
            float v = 0.0f;
            if (cc < SW && (unsigned)gx < (unsigned)WW && (unsigned)gy < (unsigned)HH)
                v = sc[gy * WW + gx];
            tile[c][r][cc] = v;
        }
    }
    __syncthreads();

    const int tx = threadIdx.x, ty = threadIdx.y;
    const int xA = x0 + 2 * tx;
    const int y  = y0 + ty;

    // Plane indices for the two pixels (exact reference bucketing).
    const float cA = coc[((size_t)b * HH + y) * WW + xA];
    const float cB = coc[((size_t)b * HH + y) * WW + xA + 1];
    int pA = 0, pB = 0;
#pragma unroll
    for (int i = 0; i < 31; i++) {
        pA += (cA > msh[i]);
        pB += (cB > msh[i]);
    }

    // Per-plane symmetric half-kernels into registers (compile-time dx index).
    float wA[16], wB[16];
#pragma unroll
    for (int j = 0; j < 16; j++) { wA[j] = gsh[pA][j]; wB[j] = gsh[pB][j]; }

    float acc[6] = {0.f, 0.f, 0.f, 0.f, 0.f, 0.f};   // [c][A|B]

    for (int dy = 0; dy < 31; dy++) {
        const int sdy = (dy < 16) ? dy : 30 - dy;
        const float gyA = gsh[pA][sdy];              // runtime dy -> shared read
        const float gyB = gsh[pB][sdy];
#pragma unroll
        for (int c = 0; c < CCH; c++) {
            const float* rp = &tile[c][ty + dy][2 * tx];
            float win[32];
#pragma unroll
            for (int j = 0; j < 16; j++) {           // 16 x LDS.64, conflict-free
                float2 t = *(const float2*)(rp + 2 * j);
                win[2 * j]     = t.x;
                win[2 * j + 1] = t.y;
            }
            float rA0 = 0.f, rA1 = 0.f, rB0 = 0.f, rB1 = 0.f;
#pragma unroll
            for (int dx = 0; dx < 31; dx++) {
                const int sj = (dx < 16) ? dx : 30 - dx;  // symmetry fold
                if (dx & 1) { rA1 += wA[sj] * win[dx]; rB1 += wB[sj] * win[dx + 1]; }
                else        { rA0 += wA[sj] * win[dx]; rB0 += wB[sj] * win[dx + 1]; }
            }
            acc[2 * c]     += gyA * (rA0 + rA1);
            acc[2 * c + 1] += gyB * (rB0 + rB1);
        }
    }

    float* ob = out + (size_t)b * CCH * HH * WW;
#pragma unroll
    for (int c = 0; c < CCH; c++) {
        float2 v;
        v.x = acc[2 * c];
        v.y = acc[2 * c + 1];
        *(float2*)(ob + ((size_t)c * HH + y) * WW + xA) = v;
    }
}

// ---------------------------------------------------------------------------
extern "C" void kernel_launch(void* const* d_in, const int* in_sizes, int n_in,
                              void* d_out, int out_size) {
    // metadata order: sharp_image [4,3,512,512], coc_map [4,1,512,512].
    const float* sharp = (const float*)d_in[0];
    const float* coc   = (const float*)d_in[1];
    if (n_in >= 2 && in_sizes[0] == BQ * HH * WW && in_sizes[1] == BQ * CCH * HH * WW) {
        // defensive: swap if ordering differs
        sharp = (const float*)d_in[1];
        coc   = (const float*)d_in[0];
    }
    float* out = (float*)d_out;

    init_weights_kernel<<<1, 32>>>();
    dim3 grid(WW / TW, HH / TH, BQ);
    dim3 block(32, 8);
    defocus_kernel<<<grid, block>>>(sharp, coc, out);
}

// round 2
// speedup vs baseline: 1.1255x; 1.1255x over previous
#include <cuda_runtime.h>
#include <math.h>

typedef unsigned long long ull;

#define BQ   4
#define CCH  3
#define HH   512
#define WW   512
#define NPL  32
#define TW   64
#define TH   16
#define HALO 15
#define SH   (TH + 2*HALO)      // 46 halo rows
#define SWP  96                 // E stream [0,48), O stream [48,96)
#define TILE_F (CCH*SH*SWP)     // 13248 floats
#define GSH_F  (NPL*33)         // 1056 floats (pad 33: bank-conflict-free)
#define SMEM_FLOATS (TILE_F + GSH_F + 32)
#define SMEM_BYTES  (SMEM_FLOATS * 4)   // 57344 B -> dynamic smem

__device__ __forceinline__ ull packf2(float lo, float hi) {
    ull r; asm("mov.b64 %0, {%1, %2};" : "=l"(r) : "f"(lo), "f"(hi)); return r;
}
__device__ __forceinline__ void unpackf2(ull v, float &lo, float &hi) {
    asm("mov.b64 {%0, %1}, %2;" : "=f"(lo), "=f"(hi) : "l"(v));
}
// packed 2-wide f32 FMA: acc = a*b + acc  (ptxas never emits FFMA2 on its own)
__device__ __forceinline__ void fma2(ull &acc, ull a, ull b) {
    asm("fma.rn.f32x2 %0, %1, %2, %0;" : "+l"(acc) : "l"(a), "l"(b));
}

__global__ void __launch_bounds__(256)
defocus_kernel(const float* __restrict__ sharp,
               const float* __restrict__ coc,
               float* __restrict__ out) {
    extern __shared__ float sm[];
    float* tile = sm;                 // [c][r][96]: even cols at +0, odd at +48
    float* gsh  = sm + TILE_F;        // [32][33] zero-padded 31-tap gaussians
    float* msh  = gsh + GSH_F;        // 31 bucket midpoints

    const int tx  = threadIdx.x;      // 0..15
    const int ty  = threadIdx.y;      // 0..15
    const int tid = ty * 16 + tx;
    const int x0  = blockIdx.x * TW;
    const int y0  = blockIdx.y * TH;
    const int b   = blockIdx.z;

    // ---- weight table: warp 0 builds it (overlaps with tile loading) ----
    if (tid < NPL) {
        const int i = tid;
        const double step = 50.0 / 31.0;
        float cocf = (float)(i * step);                 // f32 linspace value
        if (i < NPL - 1) msh[i] = (cocf + (float)((i + 1) * step)) * 0.5f;
        float row[31];
#pragma unroll
        for (int j = 0; j < 31; j++) row[j] = 0.0f;
        if (cocf < 0.5f) {
            row[15] = 1.0f;                             // identity plane
        } else {
            double cd = (double)cocf;
            int k = (int)(2.0 * cd + 1.0);
            if (!(k & 1)) k++;
            if (k > 31) k = 31;
            double sg = cd / 2.355;
            float inv2 = (float)(1.0 / (2.0 * sg * sg));
            int half = k / 2;
            float tmp[31], s = 0.0f;
            for (int j = 0; j < k; j++) {
                float c = (float)(j - half);
                float e = expf(-c * c * inv2);
                tmp[j] = e; s += e;
            }
            float invs = 1.0f / s;
            for (int j = 0; j < k; j++) row[15 - half + j] = tmp[j] * invs;
        }
        for (int j = 0; j < 31; j++) gsh[i * 33 + j] = row[j];
        gsh[i * 33 + 31] = 0.0f; gsh[i * 33 + 32] = 0.0f;
    }

    // ---- tile load, de-interleaved into E/O column streams ----
#pragma unroll
    for (int c = 0; c < CCH; c++) {
        const float* sc = sharp + ((size_t)(b * CCH + c)) * HH * WW;
        float* tc = tile + c * SH * SWP;
        for (int idx = tid; idx < SH * SWP; idx += 256) {
            int r = idx / SWP;
            int t = idx - r * SWP;                      // 0..95 (94,95 = pad)
            float v = 0.0f;
            if (t < 94) {
                int gx = x0 - HALO + t;
                int gy = y0 - HALO + r;
                if ((unsigned)gx < (unsigned)WW && (unsigned)gy < (unsigned)HH)
                    v = sc[gy * WW + gx];
            }
            tc[r * SWP + (t & 1) * 48 + (t >> 1)] = v;  // conflict-free
        }
    }
    __syncthreads();

    // ---- per-thread setup: 4 consecutive x-pixels A,B,C,D ----
    const int xA = x0 + 4 * tx;
    const int y  = y0 + ty;
    const float4 c4 = *(const float4*)(coc + ((size_t)b * HH + y) * WW + xA);
    int p0 = 0, p1 = 0, p2 = 0, p3 = 0;
#pragma unroll
    for (int i = 0; i < 31; i++) {
        float m = msh[i];
        p0 += c4.x > m; p1 += c4.y > m; p2 += c4.z > m; p3 += c4.w > m;
    }
    const float* gp0 = gsh + p0 * 33;
    const float* gp1 = gsh + p1 * 33;
    const float* gp2 = gsh + p2 * 33;
    const float* gp3 = gsh + p3 * 33;

    // packed symmetric half-kernels: (A,C) and (B,D) pairs
    ull wAC[16], wBD[16];
#pragma unroll
    for (int s = 0; s < 16; s++) {
        wAC[s] = packf2(gp0[s], gp2[s]);
        wBD[s] = packf2(gp1[s], gp3[s]);
    }

    ull acc[6] = {0, 0, 0, 0, 0, 0};   // [c]: AC pair, BD pair

    for (int dy = 0; dy < 31; dy++) {
        const int sdy = dy < 16 ? dy : 30 - dy;
        const ull gAC = packf2(gp0[sdy], gp2[sdy]);
        const ull gBD = packf2(gp1[sdy], gp3[sdy]);
#pragma unroll
        for (int c = 0; c < CCH; c++) {
            const float* rowp = tile + (c * SH + (ty + dy)) * SWP;
            const ull* pe = (const ull*)(rowp + 2 * tx);        // E stream
            const ull* po = (const ull*)(rowp + 48 + 2 * tx);   // O stream
            ull ue[9], uo[9];
#pragma unroll
            for (int m = 0; m < 9; m++) { ue[m] = pe[m]; uo[m] = po[m]; }
            ull ues[8], uos[8];
#pragma unroll
            for (int m = 0; m < 8; m++) {                       // shifted pairs
                ues[m] = (ue[m] >> 32) | (ue[m + 1] << 32);
                uos[m] = (uo[m] >> 32) | (uo[m + 1] << 32);
            }
            ull rAC = 0, rBD = 0;
#pragma unroll
            for (int d = 0; d < 31; d++) {
                const int sj = d < 16 ? d : 30 - d;
                ull a_ac, a_bd;
                if ((d & 1) == 0) {                  // even d: AC<-E, BD<-O
                    const int j = d >> 1;
                    a_ac = (j & 1) ? ues[j >> 1] : ue[j >> 1];
                    a_bd = (j & 1) ? uos[j >> 1] : uo[j >> 1];
                } else {                             // odd d: AC<-O, BD<-E(+1)
                    const int j  = (d - 1) >> 1;
                    const int j1 = j + 1;
                    a_ac = (j & 1)  ? uos[j >> 1]  : uo[j >> 1];
                    a_bd = (j1 & 1) ? ues[j1 >> 1] : ue[j1 >> 1];
                }
                fma2(rAC, wAC[sj], a_ac);
                fma2(rBD, wBD[sj], a_bd);
            }
            fma2(acc[2 * c],     gAC, rAC);
            fma2(acc[2 * c + 1], gBD, rBD);
        }
    }

    // ---- store: unpack (A,C),(B,D) -> float4 (A,B,C,D) ----
    float* ob = out + (size_t)b * CCH * HH * WW;
#pragma unroll
    for (int c = 0; c < CCH; c++) {
        float a, cc, bb, dd;
        unpackf2(acc[2 * c],     a,  cc);
        unpackf2(acc[2 * c + 1], bb, dd);
        *(float4*)(ob + ((size_t)c * HH + y) * WW + xA) = make_float4(a, bb, cc, dd);
    }
}

// ---------------------------------------------------------------------------
extern "C" void kernel_launch(void* const* d_in, const int* in_sizes, int n_in,
                              void* d_out, int out_size) {
    const float* sharp = (const float*)d_in[0];
    const float* coc   = (const float*)d_in[1];
    if (n_in >= 2 && in_sizes[0] == BQ * HH * WW && in_sizes[1] == BQ * CCH * HH * WW) {
        sharp = (const float*)d_in[1];   // defensive input-order swap
        coc   = (const float*)d_in[0];
    }
    float* out = (float*)d_out;

    cudaFuncSetAttribute(defocus_kernel,
                         cudaFuncAttributeMaxDynamicSharedMemorySize, SMEM_BYTES);
    dim3 grid(WW / TW, HH / TH, BQ);    // (8, 32, 4)
    dim3 block(16, 16);
    defocus_kernel<<<grid, block, SMEM_BYTES>>>(sharp, coc, out);
}